// round 4
// baseline (speedup 1.0000x reference)
#include <cuda_runtime.h>
#include <cstdint>
#include <cstddef>

#define TT 8192
#define D  2048
#define NE 8
#define LR 16
#define MP 16640          // 16384 pairs + 8*32 segment padding
#define ALPHA 2.0f
#define BKP 36
#define STG (128*BKP)     // floats per smem stage per operand

// ---------------- scratch (device globals; allocation-free) ----------------
__device__ __align__(256) float g_Xr  [(size_t)TT * D];
__device__ __align__(256) float g_W13r[(size_t)2 * D * D];
__device__ __align__(256) float g_Wdr [(size_t)D * D];
__device__ __align__(256) float g_B13r[(size_t)256 * D];
__device__ __align__(256) float g_B2r [(size_t)128 * D];
__device__ __align__(256) float g_H13 [(size_t)TT * 2 * D];
__device__ __align__(256) float g_U13 [(size_t)TT * 256];
__device__ __align__(256) float g_Hp  [(size_t)MP * D];
__device__ __align__(256) float g_Od  [(size_t)MP * D];
__device__ __align__(256) float g_U2  [(size_t)MP * 128];
__device__ __align__(256) float g_C   [(size_t)MP * D];
__device__ int   g_sel[TT * 2];
__device__ float g_wtk[TT * 2];
__device__ int   g_cnt[NE];
__device__ int   g_off[NE + 1];
__device__ int   g_cur[NE];
__device__ int   g_pairTok[MP];
__device__ float g_pairW[MP];
__device__ int   g_pairPos[TT * 2];

// ---------------- fp32 -> tf32 round-to-nearest (unbiased) ------------------
__global__ void round_tf32_kernel(const float* __restrict__ src,
                                  float* __restrict__ dst, int n4)
{
    int i = blockIdx.x * 256 + threadIdx.x;
    if (i < n4) {
        float4 v = ((const float4*)src)[i];
        uint4 o;
        asm("cvt.rna.tf32.f32 %0, %1;" : "=r"(o.x) : "f"(v.x));
        asm("cvt.rna.tf32.f32 %0, %1;" : "=r"(o.y) : "f"(v.y));
        asm("cvt.rna.tf32.f32 %0, %1;" : "=r"(o.z) : "f"(v.z));
        asm("cvt.rna.tf32.f32 %0, %1;" : "=r"(o.w) : "f"(v.w));
        ((uint4*)dst)[i] = o;
    }
}

__global__ void reset_kernel()
{
    int i = blockIdx.x * 256 + threadIdx.x;
    if (i < NE) g_cnt[i] = 0;
    if (i < MP) { g_pairTok[i] = -1; g_pairW[i] = 0.f; }
}

// ---------------- router: logits (fp64 accum), top-2, softmax ---------------
__global__ void router_kernel(const float* __restrict__ X,
                              const float* __restrict__ Wg)
{
    int t = (blockIdx.x * blockDim.x + threadIdx.x) >> 5;
    int lane = threadIdx.x & 31;
    if (t >= TT) return;
    const float4* x4 = (const float4*)(X + (size_t)t * D);
    double acc[NE];
#pragma unroll
    for (int e = 0; e < NE; e++) acc[e] = 0.0;
    for (int it = 0; it < 16; it++) {
        float4 xv = x4[it * 32 + lane];
#pragma unroll
        for (int e = 0; e < NE; e++) {
            float4 wv = ((const float4*)(Wg + (size_t)e * D))[it * 32 + lane];
            acc[e] += (double)xv.x * wv.x + (double)xv.y * wv.y
                    + (double)xv.z * wv.z + (double)xv.w * wv.w;
        }
    }
#pragma unroll
    for (int e = 0; e < NE; e++)
#pragma unroll
        for (int o = 16; o > 0; o >>= 1)
            acc[e] += __shfl_xor_sync(0xffffffffu, acc[e], o);
    if (lane == 0) {
        int e0 = 0; double b0 = acc[0];
#pragma unroll
        for (int e = 1; e < NE; e++) if (acc[e] > b0) { b0 = acc[e]; e0 = e; }
        int e1 = -1; double b1 = -1e300;
#pragma unroll
        for (int e = 0; e < NE; e++)
            if (e != e0 && acc[e] > b1) { b1 = acc[e]; e1 = e; }
        float ew = expf((float)(b1 - b0));
        float w0 = 1.f / (1.f + ew);
        float w1 = ew * w0;
        g_sel[t * 2] = e0; g_sel[t * 2 + 1] = e1;
        g_wtk[t * 2] = w0; g_wtk[t * 2 + 1] = w1;
        atomicAdd(&g_cnt[e0], 1);
        atomicAdd(&g_cnt[e1], 1);
    }
}

__global__ void scan_kernel()
{
    int o = 0;
    for (int e = 0; e < NE; e++) {
        g_off[e] = o; g_cur[e] = o;
        o += (g_cnt[e] + 31) & ~31;
    }
    g_off[NE] = o;
}

__global__ void assign_kernel()
{
    int i = blockIdx.x * 256 + threadIdx.x;
    if (i < TT * 2) {
        int e = g_sel[i];
        int p = atomicAdd(&g_cur[e], 1);
        g_pairTok[p] = i >> 1;
        g_pairW[p]   = g_wtk[i];
        g_pairPos[i] = p;
    }
}

// ---------------- tf32 mma.sync GEMM: C[M,N] = A[M,K] @ B[N,K]^T ------------
// 128x128x32 tiles, 256 threads (2x4 warps), double-buffered cp.async.
__global__ void __launch_bounds__(256) gemm_tf32(const float* __restrict__ A,
                                                 const float* __restrict__ B,
                                                 float* __restrict__ C,
                                                 int N, int K)
{
    extern __shared__ float sm[];
    float* sA = sm;
    float* sB = sm + 2 * STG;
    const int tid = threadIdx.x;
    uint32_t sAu = (uint32_t)__cvta_generic_to_shared(sA);
    uint32_t sBu = (uint32_t)__cvta_generic_to_shared(sB);

    const float* Ab = A + (size_t)blockIdx.y * 128 * K;
    const float* Bb = B + (size_t)blockIdx.x * 128 * K;

    const int wid = tid >> 5, lane = tid & 31;
    const int wm = wid & 1, wn = wid >> 1;
    const int g = lane >> 2, c = lane & 3;

    float acc[4][4][4];
#pragma unroll
    for (int i = 0; i < 4; i++)
#pragma unroll
        for (int j = 0; j < 4; j++)
#pragma unroll
            for (int k = 0; k < 4; k++) acc[i][j][k] = 0.f;

    const int KT = K >> 5;
#pragma unroll 1
    for (int kt = 0; kt < KT + 1; kt++) {
        if (kt < KT) {   // prefetch tile kt into stage kt&1
            int s = kt & 1;
            const float* ab = Ab + kt * 32;
            const float* bb = Bb + kt * 32;
#pragma unroll
            for (int i = 0; i < 4; i++) {
                int f = tid + i * 256;
                int r = f >> 3, kq = f & 7;
                uint32_t da = sAu + (uint32_t)(s * STG + r * BKP + kq * 4) * 4u;
                uint32_t db = sBu + (uint32_t)(s * STG + r * BKP + kq * 4) * 4u;
                const float* ga = ab + (size_t)r * K + kq * 4;
                const float* gb = bb + (size_t)r * K + kq * 4;
                asm volatile("cp.async.cg.shared.global [%0], [%1], 16;\n" :: "r"(da), "l"(ga));
                asm volatile("cp.async.cg.shared.global [%0], [%1], 16;\n" :: "r"(db), "l"(gb));
            }
            asm volatile("cp.async.commit_group;\n");
        }
        if (kt == 0) { asm volatile("cp.async.wait_group 0;\n"); __syncthreads(); continue; }
        // compute on tile kt-1 while tile kt is in flight
        const float* As = sA + ((kt - 1) & 1) * STG;
        const float* Bs = sB + ((kt - 1) & 1) * STG;
#pragma unroll
        for (int kk = 0; kk < 4; kk++) {
            unsigned af[4][4], bf[4][2];
#pragma unroll
            for (int mi = 0; mi < 4; mi++) {
                const float* p = As + (wm * 64 + mi * 16 + g) * BKP + kk * 8 + c;
                af[mi][0] = __float_as_uint(p[0]);
                af[mi][1] = __float_as_uint(p[8 * BKP]);
                af[mi][2] = __float_as_uint(p[4]);
                af[mi][3] = __float_as_uint(p[8 * BKP + 4]);
            }
#pragma unroll
            for (int ni = 0; ni < 4; ni++) {
                const float* p = Bs + (wn * 32 + ni * 8 + g) * BKP + kk * 8 + c;
                bf[ni][0] = __float_as_uint(p[0]);
                bf[ni][1] = __float_as_uint(p[4]);
            }
#pragma unroll
            for (int mi = 0; mi < 4; mi++)
#pragma unroll
                for (int ni = 0; ni < 4; ni++)
                    asm volatile(
                        "mma.sync.aligned.m16n8k8.row.col.f32.tf32.tf32.f32 "
                        "{%0,%1,%2,%3}, {%4,%5,%6,%7}, {%8,%9}, {%0,%1,%2,%3};"
                        : "+f"(acc[mi][ni][0]), "+f"(acc[mi][ni][1]),
                          "+f"(acc[mi][ni][2]), "+f"(acc[mi][ni][3])
                        : "r"(af[mi][0]), "r"(af[mi][1]), "r"(af[mi][2]), "r"(af[mi][3]),
                          "r"(bf[ni][0]), "r"(bf[ni][1]));
        }
        if (kt < KT) { asm volatile("cp.async.wait_group 0;\n"); }
        __syncthreads();
    }
    int mBase = blockIdx.y * 128 + wm * 64;
    int nBase = blockIdx.x * 128 + wn * 32;
#pragma unroll
    for (int mi = 0; mi < 4; mi++)
#pragma unroll
        for (int ni = 0; ni < 4; ni++) {
            int row0 = mBase + mi * 16 + g;
            int col  = nBase + ni * 8 + c * 2;
            *(float2*)&C[(size_t)row0 * N + col]       = make_float2(acc[mi][ni][0], acc[mi][ni][1]);
            *(float2*)&C[(size_t)(row0 + 8) * N + col] = make_float2(acc[mi][ni][2], acc[mi][ni][3]);
        }
}

// ---------------- per-pair LoRA up deltas + SwiGLU --------------------------
// grid: (MP/32, D/128); blockIdx.x = one 32-pair segment-aligned group.
__global__ void __launch_bounds__(256) pair_up_kernel(const float* __restrict__ A1,
                                                      const float* __restrict__ A3)
{
    __shared__ float sA1[128 * 17], sA3[128 * 17];
    __shared__ float sU[32][33];
    __shared__ int   sTok[32];
    __shared__ int   sE;
    int p0 = blockIdx.x * 32, col0 = blockIdx.y * 128, tid = threadIdx.x;
    if (tid < 32) sTok[tid] = g_pairTok[p0 + tid];
    if (tid == 0) {
        int e = 0;
        while (e < NE - 1 && g_off[e + 1] <= p0) e++;
        sE = e;
    }
    __syncthreads();
    int e = sE;
    {   // stage A1/A3 [128 cols x 16 r], padded 17
        int col = tid >> 1, half = tid & 1;
        const float* a1 = A1 + ((size_t)e * D + col0 + col) * LR + half * 8;
        const float* a3 = A3 + ((size_t)e * D + col0 + col) * LR + half * 8;
        float4 v0 = ((const float4*)a1)[0], v1 = ((const float4*)a1)[1];
        float* d1 = &sA1[col * 17 + half * 8];
        d1[0]=v0.x; d1[1]=v0.y; d1[2]=v0.z; d1[3]=v0.w;
        d1[4]=v1.x; d1[5]=v1.y; d1[6]=v1.z; d1[7]=v1.w;
        v0 = ((const float4*)a3)[0]; v1 = ((const float4*)a3)[1];
        float* d3 = &sA3[col * 17 + half * 8];
        d3[0]=v0.x; d3[1]=v0.y; d3[2]=v0.z; d3[3]=v0.w;
        d3[4]=v1.x; d3[5]=v1.y; d3[6]=v1.z; d3[7]=v1.w;
    }
    {   // stage per-pair U values (16 from B1 block, 16 from B3 block)
        int p = tid >> 3, j = tid & 7;
        int tok = sTok[p];
#pragma unroll
        for (int k = 0; k < 4; k++) {
            int v = j * 4 + k;
            float val = 0.f;
            if (tok >= 0) {
                int n = (v < 16) ? (e * LR + v) : (128 + e * LR + (v - 16));
                val = g_U13[(size_t)tok * 256 + n];
            }
            sU[p][v] = val;
        }
    }
    __syncthreads();
    for (int idx = tid; idx < 32 * 128; idx += 256) {
        int p = idx >> 7, col = idx & 127;
        int tok = sTok[p];
        float h1 = 0.f, h3 = 0.f;
        if (tok >= 0) {
            h1 = g_H13[(size_t)tok * 2 * D + col0 + col];
            h3 = g_H13[(size_t)tok * 2 * D + D + col0 + col];
        }
        float d1 = 0.f, d3 = 0.f;
#pragma unroll
        for (int r = 0; r < LR; r++) {
            d1 += sU[p][r]      * sA1[col * 17 + r];
            d3 += sU[p][16 + r] * sA3[col * 17 + r];
        }
        h1 += ALPHA * d1;
        h3 += ALPHA * d3;
        float s = h1 / (1.f + expf(-h1));
        float h = s * h3;
        uint32_t hr;
        asm("cvt.rna.tf32.f32 %0, %1;" : "=r"(hr) : "f"(h));
        g_Hp[(size_t)(p0 + p) * D + col0 + col] = __uint_as_float(hr);
    }
}

// ---------------- per-pair LoRA down delta + expert weight ------------------
__global__ void __launch_bounds__(256) pair_down_kernel(const float* __restrict__ A2)
{
    __shared__ float sA2[128 * 17];
    __shared__ float sU2[32][17];
    __shared__ float sW[32];
    __shared__ int   sE;
    int p0 = blockIdx.x * 32, col0 = blockIdx.y * 128, tid = threadIdx.x;
    if (tid < 32) sW[tid] = g_pairW[p0 + tid];
    if (tid == 0) {
        int e = 0;
        while (e < NE - 1 && g_off[e + 1] <= p0) e++;
        sE = e;
    }
    __syncthreads();
    int e = sE;
    {
        int col = tid >> 1, half = tid & 1;
        const float* a2 = A2 + ((size_t)e * D + col0 + col) * LR + half * 8;
        float4 v0 = ((const float4*)a2)[0], v1 = ((const float4*)a2)[1];
        float* d = &sA2[col * 17 + half * 8];
        d[0]=v0.x; d[1]=v0.y; d[2]=v0.z; d[3]=v0.w;
        d[4]=v1.x; d[5]=v1.y; d[6]=v1.z; d[7]=v1.w;
    }
    {
        int p = tid >> 3, v0 = (tid & 7) * 2;
        sU2[p][v0]     = g_U2[(size_t)(p0 + p) * 128 + e * LR + v0];
        sU2[p][v0 + 1] = g_U2[(size_t)(p0 + p) * 128 + e * LR + v0 + 1];
    }
    __syncthreads();
    for (int idx = tid; idx < 32 * 128; idx += 256) {
        int p = idx >> 7, col = idx & 127;
        float d2 = 0.f;
#pragma unroll
        for (int r = 0; r < LR; r++) d2 += sU2[p][r] * sA2[col * 17 + r];
        float od = g_Od[(size_t)(p0 + p) * D + col0 + col];
        g_C[(size_t)(p0 + p) * D + col0 + col] = sW[p] * (od + ALPHA * d2);
    }
}

// ---------------- deterministic 2-way gather --------------------------------
__global__ void gather_kernel(float* __restrict__ out)
{
    int i = blockIdx.x * 256 + threadIdx.x;      // over TT*D/4
    if (i >= TT * (D / 4)) return;
    int t = i >> 9;                              // D/4 = 512
    int c4 = i & 511;
    int pos0 = g_pairPos[t * 2], pos1 = g_pairPos[t * 2 + 1];
    float4 a = ((const float4*)(g_C + (size_t)pos0 * D))[c4];
    float4 b = ((const float4*)(g_C + (size_t)pos1 * D))[c4];
    ((float4*)(out + (size_t)t * D))[c4] =
        make_float4(a.x + b.x, a.y + b.y, a.z + b.z, a.w + b.w);
}

// ---------------- launch ----------------------------------------------------
extern "C" void kernel_launch(void* const* d_in, const int* in_sizes, int n_in,
                              void* d_out, int out_size)
{
    const float* X     = (const float*)d_in[0];
    const float* Wg    = (const float*)d_in[1];
    const float* Wup   = (const float*)d_in[2];
    const float* Wgate = (const float*)d_in[3];
    const float* Wdown = (const float*)d_in[4];
    const float* A1    = (const float*)d_in[5];
    const float* B1    = (const float*)d_in[6];
    const float* A2    = (const float*)d_in[7];
    const float* B2    = (const float*)d_in[8];
    const float* A3    = (const float*)d_in[9];
    const float* B3    = (const float*)d_in[10];
    float* out = (float*)d_out;

    static float *pXr=nullptr,*pW13r,*pWdr,*pB13r,*pB2r,*pH13,*pU13,*pHp,*pOd,*pU2,*pC;
    if (!pXr) {
        cudaGetSymbolAddress((void**)&pXr,  g_Xr);
        cudaGetSymbolAddress((void**)&pW13r,g_W13r);
        cudaGetSymbolAddress((void**)&pWdr, g_Wdr);
        cudaGetSymbolAddress((void**)&pB13r,g_B13r);
        cudaGetSymbolAddress((void**)&pB2r, g_B2r);
        cudaGetSymbolAddress((void**)&pH13, g_H13);
        cudaGetSymbolAddress((void**)&pU13, g_U13);
        cudaGetSymbolAddress((void**)&pHp,  g_Hp);
        cudaGetSymbolAddress((void**)&pOd,  g_Od);
        cudaGetSymbolAddress((void**)&pU2,  g_U2);
        cudaGetSymbolAddress((void**)&pC,   g_C);
        cudaFuncSetAttribute(gemm_tf32,
            cudaFuncAttributeMaxDynamicSharedMemorySize, 4 * STG * 4);
    }
    const int smem = 4 * STG * 4;   // 73728 B

    reset_kernel<<<(MP + 255) / 256, 256>>>();

    auto rnd = [&](const float* s, float* d, size_t n) {
        int n4 = (int)(n / 4);
        round_tf32_kernel<<<(n4 + 255) / 256, 256>>>(s, d, n4);
    };
    rnd(X,     pXr,            (size_t)TT * D);
    rnd(Wup,   pW13r,          (size_t)D * D);
    rnd(Wgate, pW13r + (size_t)D * D, (size_t)D * D);
    rnd(Wdown, pWdr,           (size_t)D * D);
    rnd(B1,    pB13r,          (size_t)128 * D);
    rnd(B3,    pB13r + (size_t)128 * D, (size_t)128 * D);
    rnd(B2,    pB2r,           (size_t)128 * D);

    router_kernel<<<TT * 32 / 256, 256>>>(X, Wg);
    scan_kernel<<<1, 1>>>();
    assign_kernel<<<(TT * 2 + 255) / 256, 256>>>();

    gemm_tf32<<<dim3(2 * D / 128, TT / 128), 256, smem>>>(pXr, pW13r, pH13, 2 * D, D);
    gemm_tf32<<<dim3(2,           TT / 128), 256, smem>>>(pXr, pB13r, pU13, 256,   D);

    pair_up_kernel<<<dim3(MP / 32, D / 128), 256>>>(A1, A3);

    gemm_tf32<<<dim3(D / 128, MP / 128), 256, smem>>>(pHp, pWdr, pOd, D,   D);
    gemm_tf32<<<dim3(1,       MP / 128), 256, smem>>>(pHp, pB2r, pU2, 128, D);

    pair_down_kernel<<<dim3(MP / 32, D / 128), 256>>>(A2);

    gather_kernel<<<(TT * (D / 4) + 255) / 256, 256>>>(out);
    (void)in_sizes; (void)n_in; (void)out_size;
}

// round 7
// speedup vs baseline: 1.8970x; 1.8970x over previous
#include <cuda_runtime.h>
#include <cuda_fp16.h>
#include <cstdint>
#include <cstddef>

#define TT 8192
#define D  2048
#define NE 8
#define LR 16
#define MP 16640          // 16384 pairs + 8*32 segment padding
#define ALPHA 2.0f
#define N13 4352          // 2*D + 256 (Wup,Wgate,B1,B3 concatenated)
#define N2  2176          // D + 128   (Wdown,B2 concatenated)

// ---------------- scratch (device globals; allocation-free) ----------------
__device__ __align__(256) __half g_Xh   [(size_t)TT * D];
__device__ __align__(256) __half g_W13B [(size_t)N13 * D];
__device__ __align__(256) __half g_Wd2  [(size_t)N2 * D];
__device__ __align__(256) __half g_Hph  [(size_t)MP * D];
__device__ __align__(256) float  g_H13u [(size_t)TT * N13];
__device__ __align__(256) float  g_Odu  [(size_t)MP * N2];
__device__ __align__(256) float  g_C    [(size_t)MP * D];
__device__ int   g_sel[TT * 2];
__device__ float g_wtk[TT * 2];
__device__ int   g_cnt[NE];
__device__ int   g_off[NE + 1];
__device__ int   g_cur[NE];
__device__ int   g_pairTok[MP];
__device__ float g_pairW[MP];
__device__ int   g_pairPos[TT * 2];

// ---------------- fp32 -> fp16 (rn) -----------------------------------------
__global__ void to_half_kernel(const float4* __restrict__ src,
                               __half2* __restrict__ dst, int n4)
{
    int i = blockIdx.x * 256 + threadIdx.x;
    if (i < n4) {
        float4 v = src[i];
        dst[2 * i]     = __floats2half2_rn(v.x, v.y);
        dst[2 * i + 1] = __floats2half2_rn(v.z, v.w);
    }
}

__global__ void reset_kernel()
{
    int i = blockIdx.x * 256 + threadIdx.x;
    if (i < NE) g_cnt[i] = 0;
    if (i < MP) { g_pairTok[i] = -1; g_pairW[i] = 0.f; }
}

// ---------------- router: logits (fp64 accum), top-2, softmax ---------------
__global__ void router_kernel(const float* __restrict__ X,
                              const float* __restrict__ Wg)
{
    int t = (blockIdx.x * blockDim.x + threadIdx.x) >> 5;
    int lane = threadIdx.x & 31;
    if (t >= TT) return;
    const float4* x4 = (const float4*)(X + (size_t)t * D);
    double acc[NE];
#pragma unroll
    for (int e = 0; e < NE; e++) acc[e] = 0.0;
    for (int it = 0; it < 16; it++) {
        float4 xv = x4[it * 32 + lane];
#pragma unroll
        for (int e = 0; e < NE; e++) {
            float4 wv = ((const float4*)(Wg + (size_t)e * D))[it * 32 + lane];
            acc[e] += (double)xv.x * wv.x + (double)xv.y * wv.y
                    + (double)xv.z * wv.z + (double)xv.w * wv.w;
        }
    }
#pragma unroll
    for (int e = 0; e < NE; e++)
#pragma unroll
        for (int o = 16; o > 0; o >>= 1)
            acc[e] += __shfl_xor_sync(0xffffffffu, acc[e], o);
    if (lane == 0) {
        int e0 = 0; double b0 = acc[0];
#pragma unroll
        for (int e = 1; e < NE; e++) if (acc[e] > b0) { b0 = acc[e]; e0 = e; }
        int e1 = -1; double b1 = -1e300;
#pragma unroll
        for (int e = 0; e < NE; e++)
            if (e != e0 && acc[e] > b1) { b1 = acc[e]; e1 = e; }
        float ew = expf((float)(b1 - b0));
        float w0 = 1.f / (1.f + ew);
        float w1 = ew * w0;
        g_sel[t * 2] = e0; g_sel[t * 2 + 1] = e1;
        g_wtk[t * 2] = w0; g_wtk[t * 2 + 1] = w1;
        atomicAdd(&g_cnt[e0], 1);
        atomicAdd(&g_cnt[e1], 1);
    }
}

__global__ void scan_kernel()
{
    int o = 0;
    for (int e = 0; e < NE; e++) {
        g_off[e] = o; g_cur[e] = o;
        o += (g_cnt[e] + 31) & ~31;
    }
    g_off[NE] = o;
}

__global__ void assign_kernel()
{
    int i = blockIdx.x * 256 + threadIdx.x;
    if (i < TT * 2) {
        int e = g_sel[i];
        int p = atomicAdd(&g_cur[e], 1);
        g_pairTok[p] = i >> 1;
        g_pairW[p]   = g_wtk[i];
        g_pairPos[i] = p;
    }
}

// ---------------- fp16 mma.sync GEMM: C[M,N] = A[M,K] @ B[N,K]^T (fp32) -----
// 128x128x64 CTA tiles, 8 warps (2m x 4n, warp tile 64x32), 3-stage cp.async,
// SW128-swizzled smem, ldmatrix fragment loads, m16n8k16 fp16 mma.
#define STAGE_BY 32768            // (128*64 + 128*64) halves * 2B
#define A_BY     16384

__device__ __forceinline__ uint32_t swz(uint32_t off) {
    return off ^ ((off >> 3) & 0x70u);
}

__global__ void __launch_bounds__(256, 2) gemm_h16(const __half* __restrict__ A,
                                                   const __half* __restrict__ B,
                                                   float* __restrict__ C,
                                                   int Nld, int K)
{
    extern __shared__ char smem[];
    const int tid = threadIdx.x, lane = tid & 31, wid = tid >> 5;
    const int wm = wid & 1, wn = wid >> 1;
    uint32_t sb;
    asm("{ .reg .u64 t; cvta.to.shared.u64 t, %1; cvt.u32.u64 %0, t; }"
        : "=r"(sb) : "l"(smem));

    const __half* Ab = A + (size_t)blockIdx.y * 128 * K;
    const __half* Bb = B + (size_t)blockIdx.x * 128 * K;
    const int KT = K >> 6;

    auto load_tile = [&](int kt, int st) {
        uint32_t base = sb + st * STAGE_BY;
#pragma unroll
        for (int i = 0; i < 8; i++) {
            int f = tid + i * 256;          // 2048 chunks of 16B; 8 chunks/row
            const __half* src;
            uint32_t off;
            if (f < 1024) {                 // A: 128 rows x 8 chunks
                int r = f >> 3, q = f & 7;
                src = Ab + (size_t)r * K + kt * 64 + q * 8;
                off = swz((uint32_t)(r * 128 + q * 16));
            } else {                        // B: 128 rows x 8 chunks
                int f2 = f - 1024;
                int r = f2 >> 3, q = f2 & 7;
                src = Bb + (size_t)r * K + kt * 64 + q * 8;
                off = A_BY + swz((uint32_t)(r * 128 + q * 16));
            }
            asm volatile("cp.async.cg.shared.global [%0], [%1], 16;"
                         :: "r"(base + off), "l"(src));
        }
        asm volatile("cp.async.commit_group;");
    };

    float acc[4][4][4];
#pragma unroll
    for (int i = 0; i < 4; i++)
#pragma unroll
        for (int j = 0; j < 4; j++)
#pragma unroll
            for (int k = 0; k < 4; k++) acc[i][j][k] = 0.f;

    load_tile(0, 0);
    load_tile(1, 1);

    const int lrow = lane & 15, lcol = (lane >> 4) << 4;

#pragma unroll 1
    for (int kt = 0; kt < KT; kt++) {
        if (kt + 1 < KT) asm volatile("cp.async.wait_group 1;");
        else             asm volatile("cp.async.wait_group 0;");
        __syncthreads();
        if (kt + 2 < KT) load_tile(kt + 2, (kt + 2) % 3);

        uint32_t sA = sb + (kt % 3) * STAGE_BY;
        uint32_t sB = sA + A_BY;
#pragma unroll
        for (int kk = 0; kk < 4; kk++) {
            uint32_t af[4][4], bf[4][2];
#pragma unroll
            for (int mi = 0; mi < 4; mi++) {
                int row = wm * 64 + mi * 16 + lrow;
                uint32_t ad = sA + swz((uint32_t)(row * 128 + kk * 32 + lcol));
                asm volatile(
                    "ldmatrix.sync.aligned.m8n8.x4.shared.b16 {%0,%1,%2,%3}, [%4];"
                    : "=r"(af[mi][0]), "=r"(af[mi][1]),
                      "=r"(af[mi][2]), "=r"(af[mi][3]) : "r"(ad));
            }
#pragma unroll
            for (int bi = 0; bi < 2; bi++) {
                int row = wn * 32 + bi * 16 + lrow;
                uint32_t bd = sB + swz((uint32_t)(row * 128 + kk * 32 + lcol));
                uint32_t r0, r1, r2, r3;
                asm volatile(
                    "ldmatrix.sync.aligned.m8n8.x4.shared.b16 {%0,%1,%2,%3}, [%4];"
                    : "=r"(r0), "=r"(r1), "=r"(r2), "=r"(r3) : "r"(bd));
                bf[2 * bi][0] = r0;     bf[2 * bi][1] = r2;
                bf[2 * bi + 1][0] = r1; bf[2 * bi + 1][1] = r3;
            }
#pragma unroll
            for (int mi = 0; mi < 4; mi++)
#pragma unroll
                for (int ni = 0; ni < 4; ni++)
                    asm volatile(
                        "mma.sync.aligned.m16n8k16.row.col.f32.f16.f16.f32 "
                        "{%0,%1,%2,%3}, {%4,%5,%6,%7}, {%8,%9}, {%0,%1,%2,%3};"
                        : "+f"(acc[mi][ni][0]), "+f"(acc[mi][ni][1]),
                          "+f"(acc[mi][ni][2]), "+f"(acc[mi][ni][3])
                        : "r"(af[mi][0]), "r"(af[mi][1]),
                          "r"(af[mi][2]), "r"(af[mi][3]),
                          "r"(bf[ni][0]), "r"(bf[ni][1]));
        }
        __syncthreads();
    }

    const int g = lane >> 2, c = lane & 3;
    int mBase = blockIdx.y * 128 + wm * 64;
    int nBase = blockIdx.x * 128 + wn * 32;
#pragma unroll
    for (int mi = 0; mi < 4; mi++)
#pragma unroll
        for (int ni = 0; ni < 4; ni++) {
            int row0 = mBase + mi * 16 + g;
            int col  = nBase + ni * 8 + c * 2;
            *(float2*)&C[(size_t)row0 * Nld + col]       = make_float2(acc[mi][ni][0], acc[mi][ni][1]);
            *(float2*)&C[(size_t)(row0 + 8) * Nld + col] = make_float2(acc[mi][ni][2], acc[mi][ni][3]);
        }
}

// ---------------- per-pair LoRA up deltas + SwiGLU (fp16 out) ---------------
__global__ void __launch_bounds__(256) pair_up_kernel(const float* __restrict__ A1,
                                                      const float* __restrict__ A3)
{
    __shared__ float sA1[128 * 17], sA3[128 * 17];
    __shared__ float sU[32][33];
    __shared__ int   sTok[32];
    __shared__ int   sE;
    int p0 = blockIdx.x * 32, col0 = blockIdx.y * 128, tid = threadIdx.x;
    if (tid < 32) sTok[tid] = g_pairTok[p0 + tid];
    if (tid == 0) {
        int e = 0;
        while (e < NE - 1 && g_off[e + 1] <= p0) e++;
        sE = e;
    }
    __syncthreads();
    int e = sE;
    {
        int col = tid >> 1, half = tid & 1;
        const float* a1 = A1 + ((size_t)e * D + col0 + col) * LR + half * 8;
        const float* a3 = A3 + ((size_t)e * D + col0 + col) * LR + half * 8;
        float4 v0 = ((const float4*)a1)[0], v1 = ((const float4*)a1)[1];
        float* d1 = &sA1[col * 17 + half * 8];
        d1[0]=v0.x; d1[1]=v0.y; d1[2]=v0.z; d1[3]=v0.w;
        d1[4]=v1.x; d1[5]=v1.y; d1[6]=v1.z; d1[7]=v1.w;
        v0 = ((const float4*)a3)[0]; v1 = ((const float4*)a3)[1];
        float* d3 = &sA3[col * 17 + half * 8];
        d3[0]=v0.x; d3[1]=v0.y; d3[2]=v0.z; d3[3]=v0.w;
        d3[4]=v1.x; d3[5]=v1.y; d3[6]=v1.z; d3[7]=v1.w;
    }
    {   // per-pair LoRA-up values live in H13u columns [4096, 4352)
        int p = tid >> 3, j = tid & 7;
        int tok = sTok[p];
#pragma unroll
        for (int k = 0; k < 4; k++) {
            int v = j * 4 + k;
            float val = 0.f;
            if (tok >= 0) {
                int n = (v < 16) ? (4096 + e * LR + v) : (4096 + 128 + e * LR + (v - 16));
                val = g_H13u[(size_t)tok * N13 + n];
            }
            sU[p][v] = val;
        }
    }
    __syncthreads();
    for (int idx = tid; idx < 32 * 128; idx += 256) {
        int p = idx >> 7, col = idx & 127;
        int tok = sTok[p];
        float h1 = 0.f, h3 = 0.f;
        if (tok >= 0) {
            h1 = g_H13u[(size_t)tok * N13 + col0 + col];
            h3 = g_H13u[(size_t)tok * N13 + D + col0 + col];
        }
        float d1 = 0.f, d3 = 0.f;
#pragma unroll
        for (int r = 0; r < LR; r++) {
            d1 += sU[p][r]      * sA1[col * 17 + r];
            d3 += sU[p][16 + r] * sA3[col * 17 + r];
        }
        h1 += ALPHA * d1;
        h3 += ALPHA * d3;
        float s = h1 / (1.f + expf(-h1));
        g_Hph[(size_t)(p0 + p) * D + col0 + col] = __float2half_rn(s * h3);
    }
}

// ---------------- per-pair LoRA down delta + expert weight ------------------
__global__ void __launch_bounds__(256) pair_down_kernel(const float* __restrict__ A2)
{
    __shared__ float sA2[128 * 17];
    __shared__ float sU2[32][17];
    __shared__ float sW[32];
    __shared__ int   sE;
    int p0 = blockIdx.x * 32, col0 = blockIdx.y * 128, tid = threadIdx.x;
    if (tid < 32) sW[tid] = g_pairW[p0 + tid];
    if (tid == 0) {
        int e = 0;
        while (e < NE - 1 && g_off[e + 1] <= p0) e++;
        sE = e;
    }
    __syncthreads();
    int e = sE;
    {
        int col = tid >> 1, half = tid & 1;
        const float* a2 = A2 + ((size_t)e * D + col0 + col) * LR + half * 8;
        float4 v0 = ((const float4*)a2)[0], v1 = ((const float4*)a2)[1];
        float* d = &sA2[col * 17 + half * 8];
        d[0]=v0.x; d[1]=v0.y; d[2]=v0.z; d[3]=v0.w;
        d[4]=v1.x; d[5]=v1.y; d[6]=v1.z; d[7]=v1.w;
    }
    {   // U2 lives in Odu columns [2048, 2176)
        int p = tid >> 3, v0 = (tid & 7) * 2;
        sU2[p][v0]     = g_Odu[(size_t)(p0 + p) * N2 + D + e * LR + v0];
        sU2[p][v0 + 1] = g_Odu[(size_t)(p0 + p) * N2 + D + e * LR + v0 + 1];
    }
    __syncthreads();
    for (int idx = tid; idx < 32 * 128; idx += 256) {
        int p = idx >> 7, col = idx & 127;
        float d2 = 0.f;
#pragma unroll
        for (int r = 0; r < LR; r++) d2 += sU2[p][r] * sA2[col * 17 + r];
        float od = g_Odu[(size_t)(p0 + p) * N2 + col0 + col];
        g_C[(size_t)(p0 + p) * D + col0 + col] = sW[p] * (od + ALPHA * d2);
    }
}

// ---------------- deterministic 2-way gather --------------------------------
__global__ void gather_kernel(float* __restrict__ out)
{
    int i = blockIdx.x * 256 + threadIdx.x;
    if (i >= TT * (D / 4)) return;
    int t = i >> 9;
    int c4 = i & 511;
    int pos0 = g_pairPos[t * 2], pos1 = g_pairPos[t * 2 + 1];
    float4 a = ((const float4*)(g_C + (size_t)pos0 * D))[c4];
    float4 b = ((const float4*)(g_C + (size_t)pos1 * D))[c4];
    ((float4*)(out + (size_t)t * D))[c4] =
        make_float4(a.x + b.x, a.y + b.y, a.z + b.z, a.w + b.w);
}

// ---------------- launch ----------------------------------------------------
extern "C" void kernel_launch(void* const* d_in, const int* in_sizes, int n_in,
                              void* d_out, int out_size)
{
    const float* X     = (const float*)d_in[0];
    const float* Wg    = (const float*)d_in[1];
    const float* Wup   = (const float*)d_in[2];
    const float* Wgate = (const float*)d_in[3];
    const float* Wdown = (const float*)d_in[4];
    const float* A1    = (const float*)d_in[5];
    const float* B1    = (const float*)d_in[6];
    const float* A2    = (const float*)d_in[7];
    const float* B2    = (const float*)d_in[8];
    const float* A3    = (const float*)d_in[9];
    const float* B3    = (const float*)d_in[10];
    float* out = (float*)d_out;

    static __half *pXh = nullptr, *pW13B, *pWd2, *pHph;
    static float  *pH13u, *pOdu;
    if (!pXh) {
        cudaGetSymbolAddress((void**)&pXh,   g_Xh);
        cudaGetSymbolAddress((void**)&pW13B, g_W13B);
        cudaGetSymbolAddress((void**)&pWd2,  g_Wd2);
        cudaGetSymbolAddress((void**)&pHph,  g_Hph);
        cudaGetSymbolAddress((void**)&pH13u, g_H13u);
        cudaGetSymbolAddress((void**)&pOdu,  g_Odu);
        cudaFuncSetAttribute(gemm_h16,
            cudaFuncAttributeMaxDynamicSharedMemorySize, 3 * STAGE_BY);
    }
    const int SMB = 3 * STAGE_BY;   // 98304

    reset_kernel<<<(MP + 255) / 256, 256>>>();

    auto cvt = [&](const float* s, __half* d, size_t n) {
        int n4 = (int)(n / 4);
        to_half_kernel<<<(n4 + 255) / 256, 256>>>((const float4*)s, (__half2*)d, n4);
    };
    cvt(X,     pXh,                      (size_t)TT * D);
    cvt(Wup,   pW13B,                    (size_t)D * D);
    cvt(Wgate, pW13B + (size_t)D * D,    (size_t)D * D);
    cvt(B1,    pW13B + (size_t)2 * D * D,(size_t)128 * D);
    cvt(B3,    pW13B + (size_t)2 * D * D + (size_t)128 * D, (size_t)128 * D);
    cvt(Wdown, pWd2,                     (size_t)D * D);
    cvt(B2,    pWd2 + (size_t)D * D,     (size_t)128 * D);

    router_kernel<<<TT * 32 / 256, 256>>>(X, Wg);
    scan_kernel<<<1, 1>>>();
    assign_kernel<<<(TT * 2 + 255) / 256, 256>>>();

    // H13u = Xh @ [Wup;Wgate;B1;B3]^T    [8192 x 4352]
    gemm_h16<<<dim3(N13 / 128, TT / 128), 256, SMB>>>(pXh, pW13B, pH13u, N13, D);

    pair_up_kernel<<<dim3(MP / 32, D / 128), 256>>>(A1, A3);

    // Odu = Hph @ [Wdown;B2]^T           [16640 x 2176]
    gemm_h16<<<dim3(N2 / 128, MP / 128), 256, SMB>>>(pHph, pWd2, pOdu, N2, D);

    pair_down_kernel<<<dim3(MP / 32, D / 128), 256>>>(A2);

    gather_kernel<<<(TT * (D / 4) + 255) / 256, 256>>>(out);
    (void)in_sizes; (void)n_in; (void)out_size;
}

// round 8
// speedup vs baseline: 2.1659x; 1.1418x over previous
#include <cuda_runtime.h>
#include <cuda_fp16.h>
#include <cstdint>
#include <cstddef>

#define TT 8192
#define D  2048
#define NE 8
#define LR 16
#define MP 16640          // 16384 pairs + 8*32 segment padding
#define ALPHA 2.0f
#define N13 4352          // 2*D + 256 (Wup,Wgate,B1,B3 concatenated)

// ---------------- scratch (device globals; allocation-free) ----------------
__device__ __align__(256) __half g_Xh   [(size_t)TT * D];
__device__ __align__(256) __half g_W13B [(size_t)N13 * D];
__device__ __align__(256) __half g_Wdh  [(size_t)D * D];
__device__ __align__(256) __half g_B2h  [(size_t)128 * D];
__device__ __align__(256) __half g_Hph  [(size_t)MP * D];
__device__ __align__(256) __half g_Hc   [(size_t)TT * D];
__device__ __align__(256) float  g_H13u [(size_t)TT * N13];
__device__ __align__(256) float  g_U2   [(size_t)MP * 128];
__device__ int   g_sel[TT * 2];
__device__ float g_wtk[TT * 2];
__device__ int   g_cnt[NE];
__device__ int   g_off[NE + 1];
__device__ int   g_cur[NE];
__device__ int   g_pairTok[MP];
__device__ int   g_pairPos[TT * 2];

// ---------------- fp32 -> fp16 (rn) -----------------------------------------
__global__ void to_half_kernel(const float4* __restrict__ src,
                               __half2* __restrict__ dst, int n4)
{
    int i = blockIdx.x * 256 + threadIdx.x;
    if (i < n4) {
        float4 v = src[i];
        dst[2 * i]     = __floats2half2_rn(v.x, v.y);
        dst[2 * i + 1] = __floats2half2_rn(v.z, v.w);
    }
}

__global__ void reset_kernel()
{
    int i = blockIdx.x * 256 + threadIdx.x;
    if (i < NE) g_cnt[i] = 0;
    if (i < MP) g_pairTok[i] = -1;
}

// ---------------- router: logits (fp64 accum), top-2, softmax ---------------
__global__ void router_kernel(const float* __restrict__ X,
                              const float* __restrict__ Wg)
{
    int t = (blockIdx.x * blockDim.x + threadIdx.x) >> 5;
    int lane = threadIdx.x & 31;
    if (t >= TT) return;
    const float4* x4 = (const float4*)(X + (size_t)t * D);
    double acc[NE];
#pragma unroll
    for (int e = 0; e < NE; e++) acc[e] = 0.0;
    for (int it = 0; it < 16; it++) {
        float4 xv = x4[it * 32 + lane];
#pragma unroll
        for (int e = 0; e < NE; e++) {
            float4 wv = ((const float4*)(Wg + (size_t)e * D))[it * 32 + lane];
            acc[e] += (double)xv.x * wv.x + (double)xv.y * wv.y
                    + (double)xv.z * wv.z + (double)xv.w * wv.w;
        }
    }
#pragma unroll
    for (int e = 0; e < NE; e++)
#pragma unroll
        for (int o = 16; o > 0; o >>= 1)
            acc[e] += __shfl_xor_sync(0xffffffffu, acc[e], o);
    if (lane == 0) {
        int e0 = 0; double b0 = acc[0];
#pragma unroll
        for (int e = 1; e < NE; e++) if (acc[e] > b0) { b0 = acc[e]; e0 = e; }
        int e1 = -1; double b1 = -1e300;
#pragma unroll
        for (int e = 0; e < NE; e++)
            if (e != e0 && acc[e] > b1) { b1 = acc[e]; e1 = e; }
        float ew = expf((float)(b1 - b0));
        float w0 = 1.f / (1.f + ew);
        float w1 = ew * w0;
        g_sel[t * 2] = e0; g_sel[t * 2 + 1] = e1;
        g_wtk[t * 2] = w0; g_wtk[t * 2 + 1] = w1;
        atomicAdd(&g_cnt[e0], 1);
        atomicAdd(&g_cnt[e1], 1);
    }
}

__global__ void scan_kernel()
{
    int o = 0;
    for (int e = 0; e < NE; e++) {
        g_off[e] = o; g_cur[e] = o;
        o += (g_cnt[e] + 31) & ~31;
    }
    g_off[NE] = o;
}

__global__ void assign_kernel()
{
    int i = blockIdx.x * 256 + threadIdx.x;
    if (i < TT * 2) {
        int e = g_sel[i];
        int p = atomicAdd(&g_cur[e], 1);
        g_pairTok[p] = i >> 1;
        g_pairPos[i] = p;
    }
}

// ---------------- fp16 mma.sync GEMM: C[M,N] = A[M,K] @ B[N,K]^T (fp32) -----
#define STAGE_BY 32768
#define A_BY     16384

__device__ __forceinline__ uint32_t swz(uint32_t off) {
    return off ^ ((off >> 3) & 0x70u);
}

__global__ void __launch_bounds__(256, 2) gemm_h16(const __half* __restrict__ A,
                                                   const __half* __restrict__ B,
                                                   float* __restrict__ C,
                                                   int Nld, int K)
{
    extern __shared__ char smem[];
    const int tid = threadIdx.x, lane = tid & 31, wid = tid >> 5;
    const int wm = wid & 1, wn = wid >> 1;
    uint32_t sb;
    asm("{ .reg .u64 t; cvta.to.shared.u64 t, %1; cvt.u32.u64 %0, t; }"
        : "=r"(sb) : "l"(smem));

    const __half* Ab = A + (size_t)blockIdx.y * 128 * K;
    const __half* Bb = B + (size_t)blockIdx.x * 128 * K;
    const int KT = K >> 6;

    auto load_tile = [&](int kt, int st) {
        uint32_t base = sb + st * STAGE_BY;
#pragma unroll
        for (int i = 0; i < 8; i++) {
            int f = tid + i * 256;
            const __half* src;
            uint32_t off;
            if (f < 1024) {
                int r = f >> 3, q = f & 7;
                src = Ab + (size_t)r * K + kt * 64 + q * 8;
                off = swz((uint32_t)(r * 128 + q * 16));
            } else {
                int f2 = f - 1024;
                int r = f2 >> 3, q = f2 & 7;
                src = Bb + (size_t)r * K + kt * 64 + q * 8;
                off = A_BY + swz((uint32_t)(r * 128 + q * 16));
            }
            asm volatile("cp.async.cg.shared.global [%0], [%1], 16;"
                         :: "r"(base + off), "l"(src));
        }
        asm volatile("cp.async.commit_group;");
    };

    float acc[4][4][4];
#pragma unroll
    for (int i = 0; i < 4; i++)
#pragma unroll
        for (int j = 0; j < 4; j++)
#pragma unroll
            for (int k = 0; k < 4; k++) acc[i][j][k] = 0.f;

    load_tile(0, 0);
    load_tile(1, 1);

    const int lrow = lane & 15, lcol = (lane >> 4) << 4;

#pragma unroll 1
    for (int kt = 0; kt < KT; kt++) {
        if (kt + 1 < KT) asm volatile("cp.async.wait_group 1;");
        else             asm volatile("cp.async.wait_group 0;");
        __syncthreads();
        if (kt + 2 < KT) load_tile(kt + 2, (kt + 2) % 3);

        uint32_t sA = sb + (kt % 3) * STAGE_BY;
        uint32_t sB = sA + A_BY;
#pragma unroll
        for (int kk = 0; kk < 4; kk++) {
            uint32_t af[4][4], bf[4][2];
#pragma unroll
            for (int mi = 0; mi < 4; mi++) {
                int row = wm * 64 + mi * 16 + lrow;
                uint32_t ad = sA + swz((uint32_t)(row * 128 + kk * 32 + lcol));
                asm volatile(
                    "ldmatrix.sync.aligned.m8n8.x4.shared.b16 {%0,%1,%2,%3}, [%4];"
                    : "=r"(af[mi][0]), "=r"(af[mi][1]),
                      "=r"(af[mi][2]), "=r"(af[mi][3]) : "r"(ad));
            }
#pragma unroll
            for (int bi = 0; bi < 2; bi++) {
                int row = wn * 32 + bi * 16 + lrow;
                uint32_t bd = sB + swz((uint32_t)(row * 128 + kk * 32 + lcol));
                uint32_t r0, r1, r2, r3;
                asm volatile(
                    "ldmatrix.sync.aligned.m8n8.x4.shared.b16 {%0,%1,%2,%3}, [%4];"
                    : "=r"(r0), "=r"(r1), "=r"(r2), "=r"(r3) : "r"(bd));
                bf[2 * bi][0] = r0;     bf[2 * bi][1] = r2;
                bf[2 * bi + 1][0] = r1; bf[2 * bi + 1][1] = r3;
            }
#pragma unroll
            for (int mi = 0; mi < 4; mi++)
#pragma unroll
                for (int ni = 0; ni < 4; ni++)
                    asm volatile(
                        "mma.sync.aligned.m16n8k16.row.col.f32.f16.f16.f32 "
                        "{%0,%1,%2,%3}, {%4,%5,%6,%7}, {%8,%9}, {%0,%1,%2,%3};"
                        : "+f"(acc[mi][ni][0]), "+f"(acc[mi][ni][1]),
                          "+f"(acc[mi][ni][2]), "+f"(acc[mi][ni][3])
                        : "r"(af[mi][0]), "r"(af[mi][1]),
                          "r"(af[mi][2]), "r"(af[mi][3]),
                          "r"(bf[ni][0]), "r"(bf[ni][1]));
        }
        __syncthreads();
    }

    const int g = lane >> 2, c = lane & 3;
    int mBase = blockIdx.y * 128 + wm * 64;
    int nBase = blockIdx.x * 128 + wn * 32;
#pragma unroll
    for (int mi = 0; mi < 4; mi++)
#pragma unroll
        for (int ni = 0; ni < 4; ni++) {
            int row0 = mBase + mi * 16 + g;
            int col  = nBase + ni * 8 + c * 2;
            *(float2*)&C[(size_t)row0 * Nld + col]       = make_float2(acc[mi][ni][0], acc[mi][ni][1]);
            *(float2*)&C[(size_t)(row0 + 8) * Nld + col] = make_float2(acc[mi][ni][2], acc[mi][ni][3]);
        }
}

// ---------------- per-pair LoRA up deltas + SwiGLU (fp16 out) ---------------
__global__ void __launch_bounds__(256) pair_up_kernel(const float* __restrict__ A1,
                                                      const float* __restrict__ A3)
{
    __shared__ float sA1[128 * 17], sA3[128 * 17];
    __shared__ float sU[32][33];
    __shared__ int   sTok[32];
    __shared__ int   sE;
    int p0 = blockIdx.x * 32, col0 = blockIdx.y * 128, tid = threadIdx.x;
    if (tid < 32) sTok[tid] = g_pairTok[p0 + tid];
    if (tid == 0) {
        int e = 0;
        while (e < NE - 1 && g_off[e + 1] <= p0) e++;
        sE = e;
    }
    __syncthreads();
    int e = sE;
    {
        int col = tid >> 1, half = tid & 1;
        const float* a1 = A1 + ((size_t)e * D + col0 + col) * LR + half * 8;
        const float* a3 = A3 + ((size_t)e * D + col0 + col) * LR + half * 8;
        float4 v0 = ((const float4*)a1)[0], v1 = ((const float4*)a1)[1];
        float* d1 = &sA1[col * 17 + half * 8];
        d1[0]=v0.x; d1[1]=v0.y; d1[2]=v0.z; d1[3]=v0.w;
        d1[4]=v1.x; d1[5]=v1.y; d1[6]=v1.z; d1[7]=v1.w;
        v0 = ((const float4*)a3)[0]; v1 = ((const float4*)a3)[1];
        float* d3 = &sA3[col * 17 + half * 8];
        d3[0]=v0.x; d3[1]=v0.y; d3[2]=v0.z; d3[3]=v0.w;
        d3[4]=v1.x; d3[5]=v1.y; d3[6]=v1.z; d3[7]=v1.w;
    }
    {   // per-pair LoRA-up values live in H13u columns [4096, 4352)
        int p = tid >> 3, j = tid & 7;
        int tok = sTok[p];
#pragma unroll
        for (int k = 0; k < 4; k++) {
            int v = j * 4 + k;
            float val = 0.f;
            if (tok >= 0) {
                int n = (v < 16) ? (4096 + e * LR + v) : (4096 + 128 + e * LR + (v - 16));
                val = g_H13u[(size_t)tok * N13 + n];
            }
            sU[p][v] = val;
        }
    }
    __syncthreads();
    for (int idx = tid; idx < 32 * 128; idx += 256) {
        int p = idx >> 7, col = idx & 127;
        int tok = sTok[p];
        float h1 = 0.f, h3 = 0.f;
        if (tok >= 0) {
            h1 = g_H13u[(size_t)tok * N13 + col0 + col];
            h3 = g_H13u[(size_t)tok * N13 + D + col0 + col];
        }
        float d1 = 0.f, d3 = 0.f;
#pragma unroll
        for (int r = 0; r < LR; r++) {
            d1 += sU[p][r]      * sA1[col * 17 + r];
            d3 += sU[p][16 + r] * sA3[col * 17 + r];
        }
        h1 += ALPHA * d1;
        h3 += ALPHA * d3;
        float s = h1 / (1.f + expf(-h1));
        g_Hph[(size_t)(p0 + p) * D + col0 + col] = __float2half_rn(s * h3);
    }
}

// ---------------- weighted 2-way combine of Hp rows (fp16 out) --------------
__global__ void combine_kernel()
{
    int i = blockIdx.x * 256 + threadIdx.x;   // over TT * (D/8)
    if (i >= TT * (D / 8)) return;
    int t = i >> 8;                            // D/8 = 256
    int c8 = i & 255;
    int pos0 = g_pairPos[t * 2], pos1 = g_pairPos[t * 2 + 1];
    float w0 = g_wtk[t * 2], w1 = g_wtk[t * 2 + 1];
    const __half2* a = (const __half2*)(g_Hph + (size_t)pos0 * D) + c8 * 4;
    const __half2* b = (const __half2*)(g_Hph + (size_t)pos1 * D) + c8 * 4;
    __half2* o = (__half2*)(g_Hc + (size_t)t * D) + c8 * 4;
#pragma unroll
    for (int j = 0; j < 4; j++) {
        float2 av = __half22float2(a[j]);
        float2 bv = __half22float2(b[j]);
        o[j] = __floats2half2_rn(w0 * av.x + w1 * bv.x, w0 * av.y + w1 * bv.y);
    }
}

// ---------------- final: out += ALPHA * sum_k w_k * U2[pos_k] @ A2[e_k]^T ---
// grid (D/128, TT/64); dynamic smem: A2 cols for ALL experts [8][16][128] fp32.
__global__ void __launch_bounds__(256) final_delta_kernel(const float* __restrict__ A2,
                                                          float* __restrict__ out)
{
    extern __shared__ float sA2[];        // [e][r][col] = e*2048 + r*128 + col
    __shared__ float sU[64][32];
    __shared__ int   sEl[64][2];
    int col0 = blockIdx.x * 128, t0 = blockIdx.y * 64, tid = threadIdx.x;

    // load A2 slices for all 8 experts: 1024 (e,col) pairs, 4 per thread
#pragma unroll
    for (int it = 0; it < 4; it++) {
        int pc = tid + it * 256;          // (e, col)
        int e = pc >> 7, col = pc & 127;
        const float4* src = (const float4*)(A2 + ((size_t)e * D + col0 + col) * LR);
#pragma unroll
        for (int j = 0; j < 4; j++) {
            float4 v = src[j];
            float* dst = &sA2[e * 2048 + (j * 4) * 128 + col];
            dst[0]   = v.x; dst[128] = v.y; dst[256] = v.z; dst[384] = v.w;
        }
    }
    // load weighted U2 values: 64 tokens x 2 pairs x 16
#pragma unroll
    for (int it = 0; it < 8; it++) {
        int idx = tid + it * 256;         // 2048
        int tok = idx >> 5, v = idx & 31;
        int k = v >> 4, r = v & 15;
        int gi = (t0 + tok) * 2 + k;
        int pos = g_pairPos[gi];
        int e   = g_sel[gi];
        sU[tok][v] = g_wtk[gi] * g_U2[(size_t)pos * 128 + e * LR + r];
        if (r == 0) sEl[tok][k] = e;
    }
    __syncthreads();

#pragma unroll 4
    for (int it = 0; it < 32; it++) {
        int idx = tid + it * 256;         // 64*128
        int tok = idx >> 7, col = idx & 127;
        float d = 0.f;
#pragma unroll
        for (int k = 0; k < 2; k++) {
            const float* a2c = &sA2[sEl[tok][k] * 2048 + col];
            const float* u = &sU[tok][k * 16];
#pragma unroll
            for (int r = 0; r < LR; r++) d += u[r] * a2c[r * 128];
        }
        size_t oidx = (size_t)(t0 + tok) * D + col0 + col;
        out[oidx] += ALPHA * d;
    }
}

// ---------------- launch ----------------------------------------------------
extern "C" void kernel_launch(void* const* d_in, const int* in_sizes, int n_in,
                              void* d_out, int out_size)
{
    const float* X     = (const float*)d_in[0];
    const float* Wg    = (const float*)d_in[1];
    const float* Wup   = (const float*)d_in[2];
    const float* Wgate = (const float*)d_in[3];
    const float* Wdown = (const float*)d_in[4];
    const float* A1    = (const float*)d_in[5];
    const float* B1    = (const float*)d_in[6];
    const float* A2    = (const float*)d_in[7];
    const float* B2    = (const float*)d_in[8];
    const float* A3    = (const float*)d_in[9];
    const float* B3    = (const float*)d_in[10];
    float* out = (float*)d_out;

    static __half *pXh = nullptr, *pW13B, *pWdh, *pB2h, *pHph, *pHc;
    static float  *pH13u, *pU2;
    if (!pXh) {
        cudaGetSymbolAddress((void**)&pXh,   g_Xh);
        cudaGetSymbolAddress((void**)&pW13B, g_W13B);
        cudaGetSymbolAddress((void**)&pWdh,  g_Wdh);
        cudaGetSymbolAddress((void**)&pB2h,  g_B2h);
        cudaGetSymbolAddress((void**)&pHph,  g_Hph);
        cudaGetSymbolAddress((void**)&pHc,   g_Hc);
        cudaGetSymbolAddress((void**)&pH13u, g_H13u);
        cudaGetSymbolAddress((void**)&pU2,   g_U2);
        cudaFuncSetAttribute(gemm_h16,
            cudaFuncAttributeMaxDynamicSharedMemorySize, 3 * STAGE_BY);
        cudaFuncSetAttribute(final_delta_kernel,
            cudaFuncAttributeMaxDynamicSharedMemorySize, 65536);
    }
    const int SMB = 3 * STAGE_BY;   // 98304

    reset_kernel<<<(MP + 255) / 256, 256>>>();

    auto cvt = [&](const float* s, __half* d, size_t n) {
        int n4 = (int)(n / 4);
        to_half_kernel<<<(n4 + 255) / 256, 256>>>((const float4*)s, (__half2*)d, n4);
    };
    cvt(X,     pXh,                      (size_t)TT * D);
    cvt(Wup,   pW13B,                    (size_t)D * D);
    cvt(Wgate, pW13B + (size_t)D * D,    (size_t)D * D);
    cvt(B1,    pW13B + (size_t)2 * D * D,(size_t)128 * D);
    cvt(B3,    pW13B + (size_t)2 * D * D + (size_t)128 * D, (size_t)128 * D);
    cvt(Wdown, pWdh,                     (size_t)D * D);
    cvt(B2,    pB2h,                     (size_t)128 * D);

    router_kernel<<<TT * 32 / 256, 256>>>(X, Wg);
    scan_kernel<<<1, 1>>>();
    assign_kernel<<<(TT * 2 + 255) / 256, 256>>>();

    // H13u = Xh @ [Wup;Wgate;B1;B3]^T    [8192 x 4352]
    gemm_h16<<<dim3(N13 / 128, TT / 128), 256, SMB>>>(pXh, pW13B, pH13u, N13, D);

    pair_up_kernel<<<dim3(MP / 32, D / 128), 256>>>(A1, A3);

    combine_kernel<<<TT * (D / 8) / 256, 256>>>();

    // U2 = Hph @ B2^T                    [16640 x 128]
    gemm_h16<<<dim3(1, MP / 128), 256, SMB>>>(pHph, pB2h, pU2, 128, D);

    // out_base = Hc @ Wdown^T            [8192 x 2048]  (writes d_out directly)
    gemm_h16<<<dim3(D / 128, TT / 128), 256, SMB>>>(pHc, pWdh, out, D, D);

    final_delta_kernel<<<dim3(D / 128, TT / 64), 256, 65536>>>(A2, out);
    (void)in_sizes; (void)n_in; (void)out_size;
}